// round 3
// baseline (speedup 1.0000x reference)
#include <cuda_runtime.h>
#include <cstdint>

#define S_    4096
#define D_    64
#define NH    16          // B*H
#define BM    32          // query rows per CTA
#define BN    128         // key rows per k-tile
#define NT    256
#define KT_PITCH 132      // padded pitch (floats) for transposed K tile
#define WS_PITCH 132      // padded pitch for exp-score tile
#define SCALE 0.18033688011112042f   // log2(e) / sqrt(64)

// dynamic smem layout (float offsets)
#define QS_OFF 0                      // 32*64   = 2048
#define KT_OFF 2048                   // 64*132  = 8448
#define VS_OFF 10496                  // 128*64  = 8192
#define WS_OFF 18688                  // 32*132  = 4224
#define RS_OFF 22912                  // 32
#define SMEM_FLOATS 22944             // 91776 bytes

__device__ __forceinline__ float ex2f(float x) {
    float y;
    asm("ex2.approx.f32 %0, %1;" : "=f"(y) : "f"(x));
    return y;
}

__global__ __launch_bounds__(NT, 2)
void attn_kernel(const float* __restrict__ Qg, const float* __restrict__ Kg,
                 const float* __restrict__ Vg, float* __restrict__ Wg,
                 float* __restrict__ Og) {
    extern __shared__ float sm[];
    float* Qs = sm + QS_OFF;
    float* Kt = sm + KT_OFF;
    float* Vs = sm + VS_OFF;
    float* Ws = sm + WS_OFF;
    float* RS = sm + RS_OFF;

    const int tid  = threadIdx.x;
    const int warp = tid >> 5;
    const int lane = tid & 31;

    const int bh = blockIdx.y;
    const int qb = blockIdx.x * BM;

    const float* Qp = Qg + ((size_t)bh * S_ + qb) * D_;
    const float* Kp = Kg + (size_t)bh * S_ * D_;
    const float* Vp = Vg + (size_t)bh * S_ * D_;
    float* Wp = Wg + (size_t)bh * S_ * S_ + (size_t)qb * S_;
    float* Op = Og + ((size_t)bh * S_ + qb) * D_;

    // ---- load Q tile (32x64), pre-scaled by log2(e)/8 ----
    #pragma unroll
    for (int i = 0; i < 2; i++) {
        int idx = tid + i * NT;               // float4 index, 0..511
        float4 v = ((const float4*)Qp)[idx];
        v.x *= SCALE; v.y *= SCALE; v.z *= SCALE; v.w *= SCALE;
        ((float4*)Qs)[idx] = v;
    }

    // QK mapping: warp owns q rows [warp*4, warp*4+4), lane owns k cols [lane*4, lane*4+4)
    const int q0 = warp * 4;
    const int k0 = lane * 4;
    // PV mapping: thread -> (q pair, d quad)
    const int qr = tid >> 4;                  // 0..15
    const int dc = tid & 15;                  // 0..15
    const int q0p = qr * 2;
    const int d0  = dc * 4;

    float4 o0 = make_float4(0.f, 0.f, 0.f, 0.f);
    float4 o1 = make_float4(0.f, 0.f, 0.f, 0.f);
    float rs[4] = {0.f, 0.f, 0.f, 0.f};      // per-lane partial rowsums (warp owns q0..q0+3)

    for (int kt = 0; kt < S_ / BN; kt++) {
        // ---- load K tile transposed + V tile ----
        const float* Ktg = Kp + (size_t)kt * BN * D_;
        const float* Vtg = Vp + (size_t)kt * BN * D_;
        #pragma unroll
        for (int i = 0; i < 8; i++) {
            int idx = tid + i * NT;           // float4 index, 0..2047
            int kk = idx >> 4;                // key row 0..127
            int d4 = (idx & 15) * 4;          // d base
            float4 kv = ((const float4*)Ktg)[idx];
            Kt[(d4 + 0) * KT_PITCH + kk] = kv.x;
            Kt[(d4 + 1) * KT_PITCH + kk] = kv.y;
            Kt[(d4 + 2) * KT_PITCH + kk] = kv.z;
            Kt[(d4 + 3) * KT_PITCH + kk] = kv.w;
            ((float4*)Vs)[idx] = ((const float4*)Vtg)[idx];
        }
        __syncthreads();

        // ---- QK^T: 4x4 register tile ----
        float4 acc[4];
        #pragma unroll
        for (int i = 0; i < 4; i++) acc[i] = make_float4(0.f, 0.f, 0.f, 0.f);

        #pragma unroll 4
        for (int d = 0; d < D_; d += 4) {
            const float4 ka = *(const float4*)(Kt + (d + 0) * KT_PITCH + k0);
            const float4 kb = *(const float4*)(Kt + (d + 1) * KT_PITCH + k0);
            const float4 kc = *(const float4*)(Kt + (d + 2) * KT_PITCH + k0);
            const float4 kd = *(const float4*)(Kt + (d + 3) * KT_PITCH + k0);
            #pragma unroll
            for (int i = 0; i < 4; i++) {
                const float4 q4 = *(const float4*)(Qs + (q0 + i) * D_ + d);
                acc[i].x = fmaf(q4.w, kd.x, fmaf(q4.z, kc.x, fmaf(q4.y, kb.x, fmaf(q4.x, ka.x, acc[i].x))));
                acc[i].y = fmaf(q4.w, kd.y, fmaf(q4.z, kc.y, fmaf(q4.y, kb.y, fmaf(q4.x, ka.y, acc[i].y))));
                acc[i].z = fmaf(q4.w, kd.z, fmaf(q4.z, kc.z, fmaf(q4.y, kb.z, fmaf(q4.x, ka.z, acc[i].z))));
                acc[i].w = fmaf(q4.w, kd.w, fmaf(q4.z, kc.w, fmaf(q4.y, kb.w, fmaf(q4.x, ka.w, acc[i].w))));
            }
        }

        // ---- exp2, rowsum partials, store (smem + gmem unnormalized) ----
        #pragma unroll
        for (int i = 0; i < 4; i++) {
            float4 e;
            e.x = ex2f(acc[i].x);
            e.y = ex2f(acc[i].y);
            e.z = ex2f(acc[i].z);
            e.w = ex2f(acc[i].w);
            rs[i] += (e.x + e.y) + (e.z + e.w);
            *(float4*)(Ws + (q0 + i) * WS_PITCH + k0) = e;
            *(float4*)(Wp + (size_t)(q0 + i) * S_ + kt * BN + k0) = e;
        }
        __syncthreads();

        // ---- PV accumulate: O[q][d] += exp(s)[q][k] * V[k][d] ----
        #pragma unroll 4
        for (int k = 0; k < BN; k++) {
            const float w0 = Ws[(q0p + 0) * WS_PITCH + k];
            const float w1 = Ws[(q0p + 1) * WS_PITCH + k];
            const float4 v = *(const float4*)(Vs + k * D_ + d0);
            o0.x = fmaf(w0, v.x, o0.x);
            o0.y = fmaf(w0, v.y, o0.y);
            o0.z = fmaf(w0, v.z, o0.z);
            o0.w = fmaf(w0, v.w, o0.w);
            o1.x = fmaf(w1, v.x, o1.x);
            o1.y = fmaf(w1, v.y, o1.y);
            o1.z = fmaf(w1, v.z, o1.z);
            o1.w = fmaf(w1, v.w, o1.w);
        }
        __syncthreads();
    }

    // ---- finalize rowsums: warp-reduce (warp exclusively owns its 4 q rows) ----
    #pragma unroll
    for (int i = 0; i < 4; i++) {
        float v = rs[i];
        v += __shfl_xor_sync(0xffffffffu, v, 16);
        v += __shfl_xor_sync(0xffffffffu, v, 8);
        v += __shfl_xor_sync(0xffffffffu, v, 4);
        v += __shfl_xor_sync(0xffffffffu, v, 2);
        v += __shfl_xor_sync(0xffffffffu, v, 1);
        rs[i] = v;
    }
    if (lane == 0) {
        RS[q0 + 0] = rs[0];
        RS[q0 + 1] = rs[1];
        RS[q0 + 2] = rs[2];
        RS[q0 + 3] = rs[3];
    }
    __syncthreads();

    // ---- write normalized output ----
    {
        const float inv0 = 1.0f / RS[q0p + 0];
        const float inv1 = 1.0f / RS[q0p + 1];
        o0.x *= inv0; o0.y *= inv0; o0.z *= inv0; o0.w *= inv0;
        o1.x *= inv1; o1.y *= inv1; o1.z *= inv1; o1.w *= inv1;
        *(float4*)(Op + (q0p + 0) * D_ + d0) = o0;
        *(float4*)(Op + (q0p + 1) * D_ + d0) = o1;
    }

    // ---- normalize weights in gmem (each thread touches only addresses it wrote) ----
    float inv[4];
    #pragma unroll
    for (int i = 0; i < 4; i++) inv[i] = 1.0f / RS[q0 + i];

    for (int kt = 0; kt < S_ / BN; kt++) {
        #pragma unroll
        for (int i = 0; i < 4; i++) {
            float4* p = (float4*)(Wp + (size_t)(q0 + i) * S_ + kt * BN + k0);
            float4 w = *p;
            w.x *= inv[i]; w.y *= inv[i]; w.z *= inv[i]; w.w *= inv[i];
            *p = w;
        }
    }
}

extern "C" void kernel_launch(void* const* d_in, const int* in_sizes, int n_in,
                              void* d_out, int out_size) {
    const float* Q = (const float*)d_in[0];
    const float* K = (const float*)d_in[1];
    const float* V = (const float*)d_in[2];
    float* W = (float*)d_out;
    float* O = (float*)d_out + (size_t)NH * S_ * S_;

    const int smem_bytes = SMEM_FLOATS * (int)sizeof(float);
    cudaFuncSetAttribute(attn_kernel, cudaFuncAttributeMaxDynamicSharedMemorySize, smem_bytes);

    dim3 grid(S_ / BM, NH);
    attn_kernel<<<grid, NT, smem_bytes>>>(Q, K, V, W, O);
}

// round 5
// speedup vs baseline: 1.0619x; 1.0619x over previous
#include <cuda_runtime.h>
#include <cstdint>

#define S_    4096
#define D_    64
#define NH    16
#define BM    64
#define BN    128
#define NT    256
#define NTILES (S_/BN)
#define SCALE 0.18033688011112042f   // log2(e) / sqrt(64)

// pre-transposed K: [bh][d][s]  (16 MiB scratch; __device__ global per allocation rules)
__device__ float KT_g[(size_t)NH * D_ * S_];

// dynamic smem layout (float offsets)
#define QT_OFF 0            // Qt[d][q]  64*64  = 4096
#define KT_OFF 4096         // Kt[d][k]  64*128 = 8192
#define VS_OFF 12288        // Vs[k][d] 128*64  = 8192
#define WS_OFF 20480        // Ws[q][k]  64*128 = 8192
#define RS_OFF 28672        // 64
#define SMEM_FLOATS 28736   // 114944 bytes -> 1 CTA/SM

__device__ __forceinline__ float ex2f(float x) {
    float y; asm("ex2.approx.f32 %0, %1;" : "=f"(y) : "f"(x)); return y;
}
__device__ __forceinline__ uint64_t dupf(float x) {
    uint64_t r; asm("mov.b64 %0, {%1, %1};" : "=l"(r) : "f"(x)); return r;
}
__device__ __forceinline__ void ffma2(uint64_t& d, uint64_t a, uint64_t b) {
    asm("fma.rn.f32x2 %0, %1, %2, %0;" : "+l"(d) : "l"(a), "l"(b));
}
__device__ __forceinline__ float2 unpk(uint64_t v) {
    float2 f; asm("mov.b64 {%0, %1}, %2;" : "=f"(f.x), "=f"(f.y) : "l"(v)); return f;
}

// ---- one-time K transpose: K[bh][s][d] -> KT_g[bh][d][s] ----
__global__ void transpose_k(const float* __restrict__ Kg) {
    __shared__ float t[32][33];
    const int bh = blockIdx.z;
    const int s0 = blockIdx.x * 32, d0 = blockIdx.y * 32;
    const float* Kp = Kg + (size_t)bh * S_ * D_;
    float* Tp = KT_g + (size_t)bh * D_ * S_;
    const int tx = threadIdx.x, ty = threadIdx.y;
    #pragma unroll
    for (int j = 0; j < 32; j += 8)
        t[ty + j][tx] = Kp[(size_t)(s0 + ty + j) * D_ + d0 + tx];
    __syncthreads();
    #pragma unroll
    for (int j = 0; j < 32; j += 8)
        Tp[(size_t)(d0 + ty + j) * S_ + s0 + tx] = t[tx][ty + j];
}

__global__ __launch_bounds__(NT, 1)
void attn_kernel(const float* __restrict__ Qg, const float* __restrict__ Vg,
                 float* __restrict__ Wg, float* __restrict__ Og) {
    extern __shared__ float sm[];
    float* Qt = sm + QT_OFF;
    float* Kt = sm + KT_OFF;
    float* Vs = sm + VS_OFF;
    float* Ws = sm + WS_OFF;
    float* RS = sm + RS_OFF;

    const int tid  = threadIdx.x;
    const int warp = tid >> 5;
    const int lane = tid & 31;
    const int bh = blockIdx.y;
    const int qb = blockIdx.x * BM;

    const float* Qp  = Qg + ((size_t)bh * S_ + qb) * D_;
    const float* KTp = KT_g + (size_t)bh * D_ * S_;
    const float* Vp  = Vg + (size_t)bh * S_ * D_;
    float* Wp = Wg + (size_t)bh * S_ * S_ + (size_t)qb * S_;
    float* Op = Og + ((size_t)bh * S_ + qb) * D_;

    // ---- load Q (64x64), scale, store transposed Qt[d][q] (one-time; conflicts OK) ----
    #pragma unroll
    for (int i = 0; i < 4; i++) {
        int idx = tid + i * NT;               // float4 index 0..1023
        int q  = idx >> 4;
        int d4 = (idx & 15) * 4;
        float4 v = ((const float4*)Qp)[idx];
        Qt[(d4 + 0) * 64 + q] = v.x * SCALE;
        Qt[(d4 + 1) * 64 + q] = v.y * SCALE;
        Qt[(d4 + 2) * 64 + q] = v.z * SCALE;
        Qt[(d4 + 3) * 64 + q] = v.w * SCALE;
    }

    const int q0  = warp * 8;                 // QK: warp owns 8 q rows
    const int k0  = lane * 4;                 // QK: lane owns 4 k cols
    const int qr4 = (tid >> 4) * 4;           // PV: 4 q rows
    const int d0  = (tid & 15) * 4;           // PV: 4 d cols

    uint64_t o[4][2];
    #pragma unroll
    for (int qi = 0; qi < 4; qi++) { o[qi][0] = 0; o[qi][1] = 0; }
    float rlo[4] = {0.f, 0.f, 0.f, 0.f};
    float rhi[4] = {0.f, 0.f, 0.f, 0.f};

    for (int kt = 0; kt < NTILES; kt++) {
        // ---- load K^T tile [64][128] (direct, conflict-free) + V tile [128][64] ----
        const float* Ktg = KTp + kt * BN;
        const float* Vtg = Vp + (size_t)kt * BN * D_;
        #pragma unroll
        for (int i = 0; i < 8; i++) {
            int idx = tid + i * NT;           // 0..2047
            int d  = idx >> 5;
            int c4 = (idx & 31) * 4;
            *(float4*)(Kt + d * BN + c4) = *(const float4*)(Ktg + (size_t)d * S_ + c4);
            ((float4*)Vs)[idx] = ((const float4*)Vtg)[idx];
        }
        __syncthreads();

        // ---- QK^T with packed f32x2: acc[j][k] = scores for q-pair (q0+2j, q0+2j+1), col k0+k ----
        uint64_t acc[4][4];
        #pragma unroll
        for (int j = 0; j < 4; j++)
            #pragma unroll
            for (int k = 0; k < 4; k++) acc[j][k] = 0;

        #pragma unroll 2
        for (int d = 0; d < D_; d++) {
            ulonglong2 qa = *(const ulonglong2*)(Qt + d * 64 + q0);      // pairs (q0,q0+1),(q0+2,q0+3)
            ulonglong2 qb2 = *(const ulonglong2*)(Qt + d * 64 + q0 + 4); // pairs (q0+4,..),(q0+6,..)
            float4 kv = *(const float4*)(Kt + d * BN + k0);
            uint64_t kd0 = dupf(kv.x), kd1 = dupf(kv.y), kd2 = dupf(kv.z), kd3 = dupf(kv.w);
            ffma2(acc[0][0], qa.x, kd0);  ffma2(acc[0][1], qa.x, kd1);
            ffma2(acc[0][2], qa.x, kd2);  ffma2(acc[0][3], qa.x, kd3);
            ffma2(acc[1][0], qa.y, kd0);  ffma2(acc[1][1], qa.y, kd1);
            ffma2(acc[1][2], qa.y, kd2);  ffma2(acc[1][3], qa.y, kd3);
            ffma2(acc[2][0], qb2.x, kd0); ffma2(acc[2][1], qb2.x, kd1);
            ffma2(acc[2][2], qb2.x, kd2); ffma2(acc[2][3], qb2.x, kd3);
            ffma2(acc[3][0], qb2.y, kd0); ffma2(acc[3][1], qb2.y, kd1);
            ffma2(acc[3][2], qb2.y, kd2); ffma2(acc[3][3], qb2.y, kd3);
        }

        // ---- exp2, rowsum partials, store unnormalized weights (smem + gmem) ----
        const int kcol = kt * BN + k0;
        #pragma unroll
        for (int j = 0; j < 4; j++) {
            float2 s0v = unpk(acc[j][0]);
            float2 s1v = unpk(acc[j][1]);
            float2 s2v = unpk(acc[j][2]);
            float2 s3v = unpk(acc[j][3]);
            float4 elo, ehi;
            elo.x = ex2f(s0v.x); elo.y = ex2f(s1v.x); elo.z = ex2f(s2v.x); elo.w = ex2f(s3v.x);
            ehi.x = ex2f(s0v.y); ehi.y = ex2f(s1v.y); ehi.z = ex2f(s2v.y); ehi.w = ex2f(s3v.y);
            rlo[j] += (elo.x + elo.y) + (elo.z + elo.w);
            rhi[j] += (ehi.x + ehi.y) + (ehi.z + ehi.w);
            const int r0 = q0 + 2 * j, r1 = r0 + 1;
            *(float4*)(Ws + r0 * BN + k0) = elo;
            *(float4*)(Ws + r1 * BN + k0) = ehi;
            *(float4*)(Wp + (size_t)r0 * S_ + kcol) = elo;
            *(float4*)(Wp + (size_t)r1 * S_ + kcol) = ehi;
        }
        __syncthreads();

        // ---- PV: o[q][d-pair] += w[q][k] * V[k][d-pair]  (packed over d) ----
        #pragma unroll 2
        for (int k4 = 0; k4 < BN / 4; k4++) {
            float wq[4][4];
            #pragma unroll
            for (int qi = 0; qi < 4; qi++)
                *(float4*)wq[qi] = *(const float4*)(Ws + (qr4 + qi) * BN + k4 * 4);
            #pragma unroll
            for (int m = 0; m < 4; m++) {
                ulonglong2 v2 = *(const ulonglong2*)(Vs + (k4 * 4 + m) * D_ + d0);
                #pragma unroll
                for (int qi = 0; qi < 4; qi++) {
                    uint64_t wd = dupf(wq[qi][m]);
                    ffma2(o[qi][0], wd, v2.x);
                    ffma2(o[qi][1], wd, v2.y);
                }
            }
        }
        __syncthreads();
    }

    // ---- warp-reduce rowsums (warp exclusively owns its 8 q rows) ----
    #pragma unroll
    for (int j = 0; j < 4; j++) {
        #pragma unroll
        for (int s = 16; s > 0; s >>= 1) {
            rlo[j] += __shfl_xor_sync(0xffffffffu, rlo[j], s);
            rhi[j] += __shfl_xor_sync(0xffffffffu, rhi[j], s);
        }
    }
    if (lane == 0) {
        #pragma unroll
        for (int j = 0; j < 4; j++) {
            RS[q0 + 2 * j]     = rlo[j];
            RS[q0 + 2 * j + 1] = rhi[j];
        }
    }
    __syncthreads();

    // ---- write normalized output ----
    #pragma unroll
    for (int qi = 0; qi < 4; qi++) {
        float inv = 1.0f / RS[qr4 + qi];
        float2 a = unpk(o[qi][0]);
        float2 b = unpk(o[qi][1]);
        float4 ov;
        ov.x = a.x * inv; ov.y = a.y * inv; ov.z = b.x * inv; ov.w = b.y * inv;
        *(float4*)(Op + (qr4 + qi) * D_ + d0) = ov;
    }

    // ---- normalize weights in gmem (each thread re-touches only addresses it wrote) ----
    float invw[8];
    #pragma unroll
    for (int j = 0; j < 4; j++) {
        invw[2 * j]     = 1.0f / rlo[j];
        invw[2 * j + 1] = 1.0f / rhi[j];
    }
    for (int kt = 0; kt < NTILES; kt++) {
        #pragma unroll
        for (int i = 0; i < 8; i++) {
            float4* p = (float4*)(Wp + (size_t)(q0 + i) * S_ + kt * BN + k0);
            float4 w = *p;
            w.x *= invw[i]; w.y *= invw[i]; w.z *= invw[i]; w.w *= invw[i];
            *p = w;
        }
    }
}

extern "C" void kernel_launch(void* const* d_in, const int* in_sizes, int n_in,
                              void* d_out, int out_size) {
    const float* Q = (const float*)d_in[0];
    const float* K = (const float*)d_in[1];
    const float* V = (const float*)d_in[2];
    float* W = (float*)d_out;
    float* O = (float*)d_out + (size_t)NH * S_ * S_;

    const int smem_bytes = SMEM_FLOATS * (int)sizeof(float);
    cudaFuncSetAttribute(attn_kernel, cudaFuncAttributeMaxDynamicSharedMemorySize, smem_bytes);

    dim3 tgrid(S_ / 32, D_ / 32, NH);
    transpose_k<<<tgrid, dim3(32, 8)>>>(K);

    dim3 grid(S_ / BM, NH);
    attn_kernel<<<grid, NT, smem_bytes>>>(Q, V, W, O);
}

// round 7
// speedup vs baseline: 1.4987x; 1.4114x over previous
#include <cuda_runtime.h>
#include <cstdint>

#define S_    4096
#define D_    64
#define NH    16
#define BM    64
#define BN    128
#define NT    256
#define NTILES (S_/BN)
#define SCALE 0.18033688011112042f   // log2(e) / sqrt(64)

// pre-transposed K: [bh][d][s]  (16 MiB scratch)
__device__ float KT_g[(size_t)NH * D_ * S_];

// dynamic smem layout (float offsets). Kt and Ws share storage (Kt dead after QK).
#define QT_OFF 0            // Qt[d][q]  64*64  = 4096
#define KT_OFF 4096         // Kt[d][k]  64*128 = 8192   (union with Ws[q][k] 64*128)
#define WS_OFF 4096
#define VS_OFF 12288        // Vs[k][d] 128*64  = 8192
#define RS_OFF 20480        // 64
#define SMEM_FLOATS 20544   // 82176 bytes -> 2 CTAs/SM

__device__ __forceinline__ float ex2f(float x) {
    float y; asm("ex2.approx.f32 %0, %1;" : "=f"(y) : "f"(x)); return y;
}
__device__ __forceinline__ uint64_t dupf(float x) {
    uint64_t r; asm("mov.b64 %0, {%1, %1};" : "=l"(r) : "f"(x)); return r;
}
__device__ __forceinline__ void ffma2(uint64_t& d, uint64_t a, uint64_t b) {
    asm("fma.rn.f32x2 %0, %1, %2, %0;" : "+l"(d) : "l"(a), "l"(b));
}
__device__ __forceinline__ float2 unpk(uint64_t v) {
    float2 f; asm("mov.b64 {%0, %1}, %2;" : "=f"(f.x), "=f"(f.y) : "l"(v)); return f;
}

// ---- one-time K transpose: K[bh][s][d] -> KT_g[bh][d][s] ----
__global__ void transpose_k(const float* __restrict__ Kg) {
    __shared__ float t[32][33];
    const int bh = blockIdx.z;
    const int s0 = blockIdx.x * 32, d0 = blockIdx.y * 32;
    const float* Kp = Kg + (size_t)bh * S_ * D_;
    float* Tp = KT_g + (size_t)bh * D_ * S_;
    const int tx = threadIdx.x, ty = threadIdx.y;
    #pragma unroll
    for (int j = 0; j < 32; j += 8)
        t[ty + j][tx] = Kp[(size_t)(s0 + ty + j) * D_ + d0 + tx];
    __syncthreads();
    #pragma unroll
    for (int j = 0; j < 32; j += 8)
        Tp[(size_t)(d0 + ty + j) * S_ + s0 + tx] = t[tx][ty + j];
}

__global__ __launch_bounds__(NT, 2)
void attn_kernel(const float* __restrict__ Qg, const float* __restrict__ Vg,
                 float* __restrict__ Wg, float* __restrict__ Og) {
    extern __shared__ float sm[];
    float* Qt = sm + QT_OFF;
    float* Kt = sm + KT_OFF;
    float* Ws = sm + WS_OFF;     // overlays Kt
    float* Vs = sm + VS_OFF;
    float* RS = sm + RS_OFF;

    const int tid  = threadIdx.x;
    const int warp = tid >> 5;
    const int lane = tid & 31;
    const int bh = blockIdx.y;
    const int qb = blockIdx.x * BM;

    const float* Qp  = Qg + ((size_t)bh * S_ + qb) * D_;
    const float* KTp = KT_g + (size_t)bh * D_ * S_;
    const float* Vp  = Vg + (size_t)bh * S_ * D_;
    float* Wp = Wg + (size_t)bh * S_ * S_ + (size_t)qb * S_;
    float* Op = Og + ((size_t)bh * S_ + qb) * D_;

    // ---- load Q (64x64), scale, store transposed Qt[d][q] ----
    #pragma unroll
    for (int i = 0; i < 4; i++) {
        int idx = tid + i * NT;               // float4 index 0..1023
        int q  = idx >> 4;
        int d4 = (idx & 15) * 4;
        float4 v = ((const float4*)Qp)[idx];
        Qt[(d4 + 0) * 64 + q] = v.x * SCALE;
        Qt[(d4 + 1) * 64 + q] = v.y * SCALE;
        Qt[(d4 + 2) * 64 + q] = v.z * SCALE;
        Qt[(d4 + 3) * 64 + q] = v.w * SCALE;
    }

    const int q0  = warp * 8;                 // QK: warp owns 8 q rows
    const int k0  = lane * 4;                 // QK: lane owns 4 k cols
    const int qr4 = (tid >> 4) * 4;           // PV: 4 q rows
    const int d0  = (tid & 15) * 4;           // PV: 4 d cols

    uint64_t o[4][2];
    #pragma unroll
    for (int qi = 0; qi < 4; qi++) { o[qi][0] = 0; o[qi][1] = 0; }
    float rlo[4] = {0.f, 0.f, 0.f, 0.f};
    float rhi[4] = {0.f, 0.f, 0.f, 0.f};

    for (int kt = 0; kt < NTILES; kt++) {
        // ---- load K^T tile [64][128] + V tile [128][64] ----
        const float* Ktg = KTp + kt * BN;
        const float* Vtg = Vp + (size_t)kt * BN * D_;
        #pragma unroll
        for (int i = 0; i < 8; i++) {
            int idx = tid + i * NT;           // 0..2047
            int d  = idx >> 5;
            int c4 = (idx & 31) * 4;
            *(float4*)(Kt + d * BN + c4) = *(const float4*)(Ktg + (size_t)d * S_ + c4);
            ((float4*)Vs)[idx] = ((const float4*)Vtg)[idx];
        }
        __syncthreads();

        // ---- QK^T with packed f32x2 ----
        uint64_t acc[4][4];
        #pragma unroll
        for (int j = 0; j < 4; j++)
            #pragma unroll
            for (int k = 0; k < 4; k++) acc[j][k] = 0;

        #pragma unroll 2
        for (int d = 0; d < D_; d++) {
            ulonglong2 qa  = *(const ulonglong2*)(Qt + d * 64 + q0);
            ulonglong2 qb2 = *(const ulonglong2*)(Qt + d * 64 + q0 + 4);
            float4 kv = *(const float4*)(Kt + d * BN + k0);
            uint64_t kd0 = dupf(kv.x), kd1 = dupf(kv.y), kd2 = dupf(kv.z), kd3 = dupf(kv.w);
            ffma2(acc[0][0], qa.x, kd0);  ffma2(acc[0][1], qa.x, kd1);
            ffma2(acc[0][2], qa.x, kd2);  ffma2(acc[0][3], qa.x, kd3);
            ffma2(acc[1][0], qa.y, kd0);  ffma2(acc[1][1], qa.y, kd1);
            ffma2(acc[1][2], qa.y, kd2);  ffma2(acc[1][3], qa.y, kd3);
            ffma2(acc[2][0], qb2.x, kd0); ffma2(acc[2][1], qb2.x, kd1);
            ffma2(acc[2][2], qb2.x, kd2); ffma2(acc[2][3], qb2.x, kd3);
            ffma2(acc[3][0], qb2.y, kd0); ffma2(acc[3][1], qb2.y, kd1);
            ffma2(acc[3][2], qb2.y, kd2); ffma2(acc[3][3], qb2.y, kd3);
        }
        __syncthreads();   // all Kt reads done; Ws may now overwrite the region

        // ---- exp2, rowsum partials, store Ws (over Kt) + unnormalized gmem W ----
        const int kcol = kt * BN + k0;
        #pragma unroll
        for (int j = 0; j < 4; j++) {
            float2 s0v = unpk(acc[j][0]);
            float2 s1v = unpk(acc[j][1]);
            float2 s2v = unpk(acc[j][2]);
            float2 s3v = unpk(acc[j][3]);
            float4 elo, ehi;
            elo.x = ex2f(s0v.x); elo.y = ex2f(s1v.x); elo.z = ex2f(s2v.x); elo.w = ex2f(s3v.x);
            ehi.x = ex2f(s0v.y); ehi.y = ex2f(s1v.y); ehi.z = ex2f(s2v.y); ehi.w = ex2f(s3v.y);
            rlo[j] += (elo.x + elo.y) + (elo.z + elo.w);
            rhi[j] += (ehi.x + ehi.y) + (ehi.z + ehi.w);
            const int r0 = q0 + 2 * j, r1 = r0 + 1;
            *(float4*)(Ws + r0 * BN + k0) = elo;
            *(float4*)(Ws + r1 * BN + k0) = ehi;
            *(float4*)(Wp + (size_t)r0 * S_ + kcol) = elo;
            *(float4*)(Wp + (size_t)r1 * S_ + kcol) = ehi;
        }
        __syncthreads();

        // ---- PV: o[q][d-pair] += w[q][k] * V[k][d-pair] ----
        #pragma unroll 2
        for (int k4 = 0; k4 < BN / 4; k4++) {
            float wq[4][4];
            #pragma unroll
            for (int qi = 0; qi < 4; qi++)
                *(float4*)wq[qi] = *(const float4*)(Ws + (qr4 + qi) * BN + k4 * 4);
            #pragma unroll
            for (int m = 0; m < 4; m++) {
                ulonglong2 v2 = *(const ulonglong2*)(Vs + (k4 * 4 + m) * D_ + d0);
                #pragma unroll
                for (int qi = 0; qi < 4; qi++) {
                    uint64_t wd = dupf(wq[qi][m]);
                    ffma2(o[qi][0], wd, v2.x);
                    ffma2(o[qi][1], wd, v2.y);
                }
            }
        }
        __syncthreads();   // protect Ws/Vs before next tile's loads
    }

    // ---- warp-reduce rowsums (warp exclusively owns its 8 q rows) ----
    #pragma unroll
    for (int j = 0; j < 4; j++) {
        #pragma unroll
        for (int s = 16; s > 0; s >>= 1) {
            rlo[j] += __shfl_xor_sync(0xffffffffu, rlo[j], s);
            rhi[j] += __shfl_xor_sync(0xffffffffu, rhi[j], s);
        }
    }
    if (lane == 0) {
        #pragma unroll
        for (int j = 0; j < 4; j++) {
            RS[q0 + 2 * j]     = rlo[j];
            RS[q0 + 2 * j + 1] = rhi[j];
        }
    }
    __syncthreads();

    // ---- write normalized output ----
    #pragma unroll
    for (int qi = 0; qi < 4; qi++) {
        float inv = 1.0f / RS[qr4 + qi];
        float2 a = unpk(o[qi][0]);
        float2 b = unpk(o[qi][1]);
        float4 ov;
        ov.x = a.x * inv; ov.y = a.y * inv; ov.z = b.x * inv; ov.w = b.y * inv;
        *(float4*)(Op + (qr4 + qi) * D_ + d0) = ov;
    }

    // ---- normalize weights in gmem (each thread re-touches only addresses it wrote) ----
    float invw[8];
    #pragma unroll
    for (int j = 0; j < 4; j++) {
        invw[2 * j]     = 1.0f / rlo[j];
        invw[2 * j + 1] = 1.0f / rhi[j];
    }
    for (int kt = 0; kt < NTILES; kt++) {
        #pragma unroll
        for (int i = 0; i < 8; i++) {
            float4* p = (float4*)(Wp + (size_t)(q0 + i) * S_ + kt * BN + k0);
            float4 w = *p;
            w.x *= invw[i]; w.y *= invw[i]; w.z *= invw[i]; w.w *= invw[i];
            *p = w;
        }
    }
}

extern "C" void kernel_launch(void* const* d_in, const int* in_sizes, int n_in,
                              void* d_out, int out_size) {
    const float* Q = (const float*)d_in[0];
    const float* K = (const float*)d_in[1];
    const float* V = (const float*)d_in[2];
    float* W = (float*)d_out;
    float* O = (float*)d_out + (size_t)NH * S_ * S_;

    const int smem_bytes = SMEM_FLOATS * (int)sizeof(float);
    cudaFuncSetAttribute(attn_kernel, cudaFuncAttributeMaxDynamicSharedMemorySize, smem_bytes);

    dim3 tgrid(S_ / 32, D_ / 32, NH);
    transpose_k<<<tgrid, dim3(32, 8)>>>(K);

    dim3 grid(S_ / BM, NH);
    attn_kernel<<<grid, NT, smem_bytes>>>(Q, V, W, O);
}

// round 12
// speedup vs baseline: 2.4539x; 1.6373x over previous
#include <cuda_runtime.h>
#include <cstdint>

#define S_    4096
#define D_    64
#define NH    16
#define BM    128
#define BN    128
#define NT    256
#define NTILES (S_/BN)
#define SCALE 0.18033688011112042f   // log2(e)/sqrt(64)

// smem pitches (floats) — chosen so fragment LDS is bank-conflict-free
#define QP 68
#define KP 68
#define VP 72
#define PP 132

// smem float offsets
#define QS_OFF 0                 // Q  128*68  = 8704
#define KS_OFF 8704              // K  128*68  (overlaid by P)
#define PS_OFF 8704              // P  128*132 = 16896
#define VS_OFF 25600             // V  128*72  = 9216
#define RS_OFF 34816             // rowsum halves 2*128
#define SMEM_FLOATS 35072        // 140288 bytes -> 1 CTA/SM

__device__ __forceinline__ float ex2f(float x) {
    float y; asm("ex2.approx.f32 %0, %1;" : "=f"(y) : "f"(x)); return y;
}
__device__ __forceinline__ float tf32r(float x) {
    uint32_t y; asm("cvt.rna.tf32.f32 %0, %1;" : "=r"(y) : "f"(x));
    return __uint_as_float(y);
}
// D = A(16x8,tf32,row) * B(8x8,tf32,col) + D  (fp32 accum)
__device__ __forceinline__ void mma8(float* c, const uint32_t* a, const uint32_t* b) {
    asm volatile(
        "mma.sync.aligned.m16n8k8.row.col.f32.tf32.tf32.f32 "
        "{%0,%1,%2,%3}, {%4,%5,%6,%7}, {%8,%9}, {%0,%1,%2,%3};"
        : "+f"(c[0]), "+f"(c[1]), "+f"(c[2]), "+f"(c[3])
        : "r"(a[0]), "r"(a[1]), "r"(a[2]), "r"(a[3]), "r"(b[0]), "r"(b[1]));
}

__global__ __launch_bounds__(NT, 1)
void attn_mma(const float* __restrict__ Qg, const float* __restrict__ Kg,
              const float* __restrict__ Vg, float* __restrict__ Wg,
              float* __restrict__ Og) {
    extern __shared__ float sm[];
    float* Qs = sm + QS_OFF;
    float* Ks = sm + KS_OFF;
    float* Ps = sm + PS_OFF;
    float* Vs = sm + VS_OFF;
    float* RS = sm + RS_OFF;

    const int tid  = threadIdx.x;
    const int warp = tid >> 5;
    const int lane = tid & 31;
    const int g    = lane >> 2;      // group id (0..7)
    const int tig  = lane & 3;       // thread in group (0..3)
    const int bh = blockIdx.y, qb = blockIdx.x * BM;

    const float* Qp = Qg + ((size_t)bh * S_ + qb) * D_;
    const float* Kp = Kg + (size_t)bh * S_ * D_;
    const float* Vp = Vg + (size_t)bh * S_ * D_;
    float* Wp = Wg + (size_t)bh * S_ * S_ + (size_t)qb * S_;
    float* Op = Og + ((size_t)bh * S_ + qb) * D_;

    // ---- load Q (128x64), scale + tf32-round ----
    #pragma unroll
    for (int i = 0; i < 8; i++) {
        int idx = tid + i * NT;               // float4 idx 0..2047
        int r = idx >> 4, c4 = (idx & 15) * 4;
        float4 v = ((const float4*)Qp)[idx];
        v.x = tf32r(v.x * SCALE); v.y = tf32r(v.y * SCALE);
        v.z = tf32r(v.z * SCALE); v.w = tf32r(v.w * SCALE);
        *(float4*)(Qs + r * QP + c4) = v;
    }

    const int mw  = warp & 3;        // m-block (32 q rows)
    const int nw  = warp >> 2;       // n-half
    const int q0w = mw * 32;
    const int n0w = nw * 64;         // QK: k-col half
    const int d0w = nw * 32;         // PV: d-col half

    float accO[2][4][4];             // persistent PV accum
    #pragma unroll
    for (int mt = 0; mt < 2; mt++)
        #pragma unroll
        for (int nt = 0; nt < 4; nt++)
            #pragma unroll
            for (int i = 0; i < 4; i++) accO[mt][nt][i] = 0.f;
    float rsum[2][2] = {{0.f, 0.f}, {0.f, 0.f}};   // [mt][row-half]

    for (int kt = 0; kt < NTILES; kt++) {
        __syncthreads();   // prev tile's P/V consumers done

        // ---- load K tile [128k x 64d] + V tile [128k x 64d], tf32-round ----
        const float* Ktg = Kp + (size_t)kt * BN * D_;
        const float* Vtg = Vp + (size_t)kt * BN * D_;
        #pragma unroll
        for (int i = 0; i < 8; i++) {
            int idx = tid + i * NT;
            int r = idx >> 4, c4 = (idx & 15) * 4;
            float4 k = ((const float4*)Ktg)[idx];
            k.x = tf32r(k.x); k.y = tf32r(k.y); k.z = tf32r(k.z); k.w = tf32r(k.w);
            *(float4*)(Ks + r * KP + c4) = k;
            float4 v = ((const float4*)Vtg)[idx];
            v.x = tf32r(v.x); v.y = tf32r(v.y); v.z = tf32r(v.z); v.w = tf32r(v.w);
            *(float4*)(Vs + r * VP + c4) = v;
        }
        __syncthreads();

        // ---- QK^T: warp computes S[32q x 64k] ----
        float accS[2][8][4];
        #pragma unroll
        for (int mt = 0; mt < 2; mt++)
            #pragma unroll
            for (int nt = 0; nt < 8; nt++)
                #pragma unroll
                for (int i = 0; i < 4; i++) accS[mt][nt][i] = 0.f;

        #pragma unroll
        for (int ks = 0; ks < 8; ks++) {
            const int d = ks * 8;
            uint32_t A[2][4];
            #pragma unroll
            for (int mt = 0; mt < 2; mt++) {
                const int r0 = q0w + mt * 16 + g;
                A[mt][0] = __float_as_uint(Qs[r0 * QP + d + tig]);
                A[mt][1] = __float_as_uint(Qs[(r0 + 8) * QP + d + tig]);
                A[mt][2] = __float_as_uint(Qs[r0 * QP + d + tig + 4]);
                A[mt][3] = __float_as_uint(Qs[(r0 + 8) * QP + d + tig + 4]);
            }
            #pragma unroll
            for (int nt = 0; nt < 8; nt++) {
                const int n0 = n0w + nt * 8 + g;
                uint32_t B[2];
                B[0] = __float_as_uint(Ks[n0 * KP + d + tig]);
                B[1] = __float_as_uint(Ks[n0 * KP + d + tig + 4]);
                mma8(accS[0][nt], A[0], B);
                mma8(accS[1][nt], A[1], B);
            }
        }
        __syncthreads();   // K reads done -> P may overwrite

        // ---- epilogue: exp2, rowsum partials, tf32-round, STS P ----
        #pragma unroll
        for (int mt = 0; mt < 2; mt++) {
            const int r0 = q0w + mt * 16 + g;
            #pragma unroll
            for (int nt = 0; nt < 8; nt++) {
                float e0 = ex2f(accS[mt][nt][0]);
                float e1 = ex2f(accS[mt][nt][1]);
                float e2 = ex2f(accS[mt][nt][2]);
                float e3 = ex2f(accS[mt][nt][3]);
                rsum[mt][0] += e0 + e1;
                rsum[mt][1] += e2 + e3;
                const int c = n0w + nt * 8 + tig * 2;
                *(float2*)(Ps + r0 * PP + c) = make_float2(tf32r(e0), tf32r(e1));
                *(float2*)(Ps + (r0 + 8) * PP + c) = make_float2(tf32r(e2), tf32r(e3));
            }
        }
        __syncthreads();   // P visible to all warps

        // ---- unnormalized W store (fire DRAM early, overlaps PV mma) ----
        #pragma unroll
        for (int it = 0; it < 16; it++) {
            const int r = warp * 16 + it;
            float4 v = *(const float4*)(Ps + r * PP + lane * 4);
            *(float4*)(Wp + (size_t)r * S_ + kt * BN + lane * 4) = v;
        }

        // ---- PV: O[32q x 32d] += P[32q x 128k] @ V[128k x 32d] ----
        #pragma unroll
        for (int ks = 0; ks < 16; ks++) {
            const int kk = ks * 8;
            uint32_t A[2][4];
            #pragma unroll
            for (int mt = 0; mt < 2; mt++) {
                const int r0 = q0w + mt * 16 + g;
                A[mt][0] = __float_as_uint(Ps[r0 * PP + kk + tig]);
                A[mt][1] = __float_as_uint(Ps[(r0 + 8) * PP + kk + tig]);
                A[mt][2] = __float_as_uint(Ps[r0 * PP + kk + tig + 4]);
                A[mt][3] = __float_as_uint(Ps[(r0 + 8) * PP + kk + tig + 4]);
            }
            #pragma unroll
            for (int nt = 0; nt < 4; nt++) {
                const int n0 = d0w + nt * 8 + g;
                uint32_t B[2];
                B[0] = __float_as_uint(Vs[(kk + tig) * VP + n0]);
                B[1] = __float_as_uint(Vs[(kk + tig + 4) * VP + n0]);
                mma8(accO[0][nt], A[0], B);
                mma8(accO[1][nt], A[1], B);
            }
        }
    }

    // ---- publish half-row sums (quad reduce, unique writer per (row, half)) ----
    #pragma unroll
    for (int mt = 0; mt < 2; mt++)
        #pragma unroll
        for (int h = 0; h < 2; h++) {
            float v = rsum[mt][h];
            v += __shfl_xor_sync(0xffffffffu, v, 1);
            v += __shfl_xor_sync(0xffffffffu, v, 2);
            rsum[mt][h] = v;
        }
    if (tig == 0) {
        RS[nw * 128 + q0w + g]      = rsum[0][0];
        RS[nw * 128 + q0w + g + 8]  = rsum[0][1];
        RS[nw * 128 + q0w + 16 + g]     = rsum[1][0];
        RS[nw * 128 + q0w + 16 + g + 8] = rsum[1][1];
    }
    __syncthreads();

    // ---- write normalized O ----
    #pragma unroll
    for (int mt = 0; mt < 2; mt++) {
        const int r0 = q0w + mt * 16 + g;
        const float inv0 = 1.0f / (RS[r0] + RS[128 + r0]);
        const float inv1 = 1.0f / (RS[r0 + 8] + RS[128 + r0 + 8]);
        #pragma unroll
        for (int nt = 0; nt < 4; nt++) {
            const int c = d0w + nt * 8 + tig * 2;
            *(float2*)(Op + (size_t)r0 * D_ + c) =
                make_float2(accO[0][nt][0] * inv0, accO[0][nt][1] * inv0);
            *(float2*)(Op + (size_t)(r0 + 8) * D_ + c) =
                make_float2(accO[0][nt][2] * inv1, accO[0][nt][3] * inv1);
        }
    }
    // second m-tile rows
    {
        const int r0 = q0w + 16 + g;
        const float inv0 = 1.0f / (RS[r0] + RS[128 + r0]);
        const float inv1 = 1.0f / (RS[r0 + 8] + RS[128 + r0 + 8]);
        #pragma unroll
        for (int nt = 0; nt < 4; nt++) {
            const int c = d0w + nt * 8 + tig * 2;
            *(float2*)(Op + (size_t)r0 * D_ + c) =
                make_float2(accO[1][nt][0] * inv0, accO[1][nt][1] * inv0);
            *(float2*)(Op + (size_t)(r0 + 8) * D_ + c) =
                make_float2(accO[1][nt][2] * inv1, accO[1][nt][3] * inv1);
        }
    }

    // ---- normalize W in gmem (coalesced readback) ----
    for (int r = 0; r < BM; r++) {
        const float inv = 1.0f / (RS[r] + RS[128 + r]);
        float4* rowp = (float4*)(Wp + (size_t)r * S_);
        #pragma unroll
        for (int i = 0; i < 4; i++) {
            int c4 = tid + i * NT;
            float4 v = rowp[c4];
            v.x *= inv; v.y *= inv; v.z *= inv; v.w *= inv;
            rowp[c4] = v;
        }
    }
}

extern "C" void kernel_launch(void* const* d_in, const int* in_sizes, int n_in,
                              void* d_out, int out_size) {
    const float* Q = (const float*)d_in[0];
    const float* K = (const float*)d_in[1];
    const float* V = (const float*)d_in[2];
    float* W = (float*)d_out;
    float* O = (float*)d_out + (size_t)NH * S_ * S_;

    const int smem_bytes = SMEM_FLOATS * (int)sizeof(float);
    cudaFuncSetAttribute(attn_mma, cudaFuncAttributeMaxDynamicSharedMemorySize, smem_bytes);

    dim3 grid(S_ / BM, NH);
    attn_mma<<<grid, NT, smem_bytes>>>(Q, K, V, W, O);
}

// round 13
// speedup vs baseline: 3.2581x; 1.3278x over previous
#include <cuda_runtime.h>
#include <cstdint>

#define S_    4096
#define D_    64
#define NH    16
#define BM    128
#define BN    128
#define NT    256
#define NTILES (S_/BN)
#define SCALE 0.18033688011112042f   // log2(e)/sqrt(64)

// smem pitches (floats) — conflict-free for fragment LDS
#define QP 68
#define KP 68
#define VP 72
#define PP 132

// smem float offsets
#define QS_OFF 0            // Q  128*68 = 8704
#define KS_OFF 8704         // K  128*68 = 8704   (pass-2 K; pass-1 K buf A)
#define PS_OFF 17408        // P  128*132 = 16896 (pass-1 K buf B lives here too)
#define VS_OFF 34304        // V  2 x 128*72 = 18432 (double-buffered)
#define VSTRIDE 9216
#define RS_OFF 52736        // 256 rowsum halves
#define SMEM_FLOATS 52992   // 211968 B -> 1 CTA/SM

// pre-rounded inputs (prologue kernel): Qr = rna(Q*SCALE), Kr/Vr = rna(K/V)
__device__ __align__(16) float Qr[(size_t)NH * S_ * D_];
__device__ __align__(16) float Kr[(size_t)NH * S_ * D_];
__device__ __align__(16) float Vr[(size_t)NH * S_ * D_];

__device__ __forceinline__ float ex2f(float x) {
    float y; asm("ex2.approx.f32 %0, %1;" : "=f"(y) : "f"(x)); return y;
}
__device__ __forceinline__ float tf32r(float x) {
    uint32_t y; asm("cvt.rna.tf32.f32 %0, %1;" : "=r"(y) : "f"(x));
    return __uint_as_float(y);
}
__device__ __forceinline__ uint32_t s2u(const void* p) {
    uint32_t a;
    asm("{ .reg .u64 t; cvta.to.shared.u64 t, %1; cvt.u32.u64 %0, t; }" : "=r"(a) : "l"(p));
    return a;
}
__device__ __forceinline__ void cpa16(uint32_t saddr, const void* gaddr) {
    asm volatile("cp.async.cg.shared.global [%0], [%1], 16;" :: "r"(saddr), "l"(gaddr));
}
#define CPA_COMMIT() asm volatile("cp.async.commit_group;" ::: "memory")
#define CPA_WAIT0()  asm volatile("cp.async.wait_group 0;" ::: "memory")

// D = A(16x8,tf32,row) * B(8x8,tf32,col) + D  (fp32 accum)
__device__ __forceinline__ void mma8(float* c, const uint32_t* a, const uint32_t* b) {
    asm volatile(
        "mma.sync.aligned.m16n8k8.row.col.f32.tf32.tf32.f32 "
        "{%0,%1,%2,%3}, {%4,%5,%6,%7}, {%8,%9}, {%0,%1,%2,%3};"
        : "+f"(c[0]), "+f"(c[1]), "+f"(c[2]), "+f"(c[3])
        : "r"(a[0]), "r"(a[1]), "r"(a[2]), "r"(a[3]), "r"(b[0]), "r"(b[1]));
}

// ---- prologue: pre-round inputs to tf32 (Q also pre-scaled) ----
__global__ void prep(const float* __restrict__ Q, const float* __restrict__ K,
                     const float* __restrict__ V) {
    size_t idx = (size_t)blockIdx.x * blockDim.x + threadIdx.x;   // float4 idx, exact grid
    float4 q = ((const float4*)Q)[idx];
    q.x = tf32r(q.x * SCALE); q.y = tf32r(q.y * SCALE);
    q.z = tf32r(q.z * SCALE); q.w = tf32r(q.w * SCALE);
    ((float4*)Qr)[idx] = q;
    float4 k = ((const float4*)K)[idx];
    k.x = tf32r(k.x); k.y = tf32r(k.y); k.z = tf32r(k.z); k.w = tf32r(k.w);
    ((float4*)Kr)[idx] = k;
    float4 v = ((const float4*)V)[idx];
    v.x = tf32r(v.x); v.y = tf32r(v.y); v.z = tf32r(v.z); v.w = tf32r(v.w);
    ((float4*)Vr)[idx] = v;
}

__global__ __launch_bounds__(NT, 1)
void attn2(float* __restrict__ Wg, float* __restrict__ Og) {
    extern __shared__ float sm[];
    const uint32_t sb = s2u(sm);
    float* Qs = sm + QS_OFF;
    float* Ps = sm + PS_OFF;
    float* RS = sm + RS_OFF;

    const int tid  = threadIdx.x;
    const int warp = tid >> 5;
    const int lane = tid & 31;
    const int g    = lane >> 2;
    const int tig  = lane & 3;
    const int bh = blockIdx.y, qb = blockIdx.x * BM;

    const float* Qp = Qr + ((size_t)bh * S_ + qb) * D_;
    const float* Kp = Kr + (size_t)bh * S_ * D_;
    const float* Vp = Vr + (size_t)bh * S_ * D_;
    float* Wp = Wg + (size_t)bh * S_ * S_ + (size_t)qb * S_;
    float* Op = Og + ((size_t)bh * S_ + qb) * D_;

    auto cpaK = [&](int kt, uint32_t dst_off) {
        const char* Ktg = (const char*)(Kp + (size_t)kt * BN * D_);
        #pragma unroll
        for (int i = 0; i < 8; i++) {
            int idx = tid + i * NT;
            int r = idx >> 4, c4 = (idx & 15) * 4;
            cpa16(sb + (uint32_t)(dst_off + r * KP + c4) * 4, Ktg + (size_t)idx * 16);
        }
    };
    auto cpaV = [&](int kt, int vb) {
        const char* Vtg = (const char*)(Vp + (size_t)kt * BN * D_);
        #pragma unroll
        for (int i = 0; i < 8; i++) {
            int idx = tid + i * NT;
            int r = idx >> 4, c4 = (idx & 15) * 4;
            cpa16(sb + (uint32_t)(VS_OFF + vb * VSTRIDE + r * VP + c4) * 4,
                  Vtg + (size_t)idx * 16);
        }
    };

    // ---- load Q (already scaled+rounded) ----
    #pragma unroll
    for (int i = 0; i < 8; i++) {
        int idx = tid + i * NT;
        int r = idx >> 4, c4 = (idx & 15) * 4;
        *(float4*)(Qs + r * QP + c4) = ((const float4*)Qp)[idx];
    }

    const int mw  = warp & 3;
    const int nw  = warp >> 2;
    const int q0w = mw * 32;
    const int n0w = nw * 64;
    const int d0w = nw * 32;

    // =============== PASS 1: rowsums only (K double-buffered, full overlap) ===============
    cpaK(0, KS_OFF); CPA_COMMIT();
    float rs1[2][2] = {{0.f, 0.f}, {0.f, 0.f}};

    for (int kt = 0; kt < NTILES; kt++) {
        CPA_WAIT0();
        __syncthreads();
        if (kt + 1 < NTILES) { cpaK(kt + 1, ((kt + 1) & 1) ? PS_OFF : KS_OFF); CPA_COMMIT(); }
        const float* kb = sm + ((kt & 1) ? PS_OFF : KS_OFF);

        float accS[2][8][4];
        #pragma unroll
        for (int mt = 0; mt < 2; mt++)
            #pragma unroll
            for (int nt = 0; nt < 8; nt++)
                #pragma unroll
                for (int i = 0; i < 4; i++) accS[mt][nt][i] = 0.f;

        #pragma unroll
        for (int ks = 0; ks < 8; ks++) {
            const int d = ks * 8;
            uint32_t A[2][4];
            #pragma unroll
            for (int mt = 0; mt < 2; mt++) {
                const int r0 = q0w + mt * 16 + g;
                A[mt][0] = __float_as_uint(Qs[r0 * QP + d + tig]);
                A[mt][1] = __float_as_uint(Qs[(r0 + 8) * QP + d + tig]);
                A[mt][2] = __float_as_uint(Qs[r0 * QP + d + tig + 4]);
                A[mt][3] = __float_as_uint(Qs[(r0 + 8) * QP + d + tig + 4]);
            }
            #pragma unroll
            for (int nt = 0; nt < 8; nt++) {
                const int n0 = n0w + nt * 8 + g;
                uint32_t B[2];
                B[0] = __float_as_uint(kb[n0 * KP + d + tig]);
                B[1] = __float_as_uint(kb[n0 * KP + d + tig + 4]);
                mma8(accS[0][nt], A[0], B);
                mma8(accS[1][nt], A[1], B);
            }
        }
        #pragma unroll
        for (int mt = 0; mt < 2; mt++)
            #pragma unroll
            for (int nt = 0; nt < 8; nt++) {
                rs1[mt][0] += ex2f(accS[mt][nt][0]) + ex2f(accS[mt][nt][1]);
                rs1[mt][1] += ex2f(accS[mt][nt][2]) + ex2f(accS[mt][nt][3]);
            }
    }

    // prefetch pass-2 tile 0 (K into Ks, V into buf 0) while reducing rowsums
    cpaK(0, KS_OFF); CPA_COMMIT();
    cpaV(0, 0);      CPA_COMMIT();

    #pragma unroll
    for (int mt = 0; mt < 2; mt++)
        #pragma unroll
        for (int h = 0; h < 2; h++) {
            float v = rs1[mt][h];
            v += __shfl_xor_sync(0xffffffffu, v, 1);
            v += __shfl_xor_sync(0xffffffffu, v, 2);
            rs1[mt][h] = v;
        }
    if (tig == 0) {
        #pragma unroll
        for (int mt = 0; mt < 2; mt++)
            #pragma unroll
            for (int h = 0; h < 2; h++)
                RS[nw * 128 + q0w + mt * 16 + g + h * 8] = rs1[mt][h];
    }
    __syncthreads();

    float inv[2][2];
    #pragma unroll
    for (int mt = 0; mt < 2; mt++)
        #pragma unroll
        for (int h = 0; h < 2; h++) {
            const int r = q0w + mt * 16 + g + h * 8;
            inv[mt][h] = 1.0f / (RS[r] + RS[128 + r]);
        }

    // =============== PASS 2: normalized W store + PV ===============
    float accO[2][4][4];
    #pragma unroll
    for (int mt = 0; mt < 2; mt++)
        #pragma unroll
        for (int nt = 0; nt < 4; nt++)
            #pragma unroll
            for (int i = 0; i < 4; i++) accO[mt][nt][i] = 0.f;

    for (int kt = 0; kt < NTILES; kt++) {
        CPA_WAIT0();            // K(kt) + V(kt) resident
        __syncthreads();        // visible to all warps; prev-tile P/V readers done
        if (kt + 1 < NTILES) { cpaV(kt + 1, (kt + 1) & 1); CPA_COMMIT(); }

        // ---- QK^T ----
        float accS[2][8][4];
        #pragma unroll
        for (int mt = 0; mt < 2; mt++)
            #pragma unroll
            for (int nt = 0; nt < 8; nt++)
                #pragma unroll
                for (int i = 0; i < 4; i++) accS[mt][nt][i] = 0.f;

        const float* kb = sm + KS_OFF;
        #pragma unroll
        for (int ks = 0; ks < 8; ks++) {
            const int d = ks * 8;
            uint32_t A[2][4];
            #pragma unroll
            for (int mt = 0; mt < 2; mt++) {
                const int r0 = q0w + mt * 16 + g;
                A[mt][0] = __float_as_uint(Qs[r0 * QP + d + tig]);
                A[mt][1] = __float_as_uint(Qs[(r0 + 8) * QP + d + tig]);
                A[mt][2] = __float_as_uint(Qs[r0 * QP + d + tig + 4]);
                A[mt][3] = __float_as_uint(Qs[(r0 + 8) * QP + d + tig + 4]);
            }
            #pragma unroll
            for (int nt = 0; nt < 8; nt++) {
                const int n0 = n0w + nt * 8 + g;
                uint32_t B[2];
                B[0] = __float_as_uint(kb[n0 * KP + d + tig]);
                B[1] = __float_as_uint(kb[n0 * KP + d + tig + 4]);
                mma8(accS[0][nt], A[0], B);
                mma8(accS[1][nt], A[1], B);
            }
        }
        __syncthreads();        // Ks free -> prefetch next K
        if (kt + 1 < NTILES) { cpaK(kt + 1, KS_OFF); CPA_COMMIT(); }

        // ---- epilogue: exp2, normalize, STG W once, STS P (tf32) ----
        const int kcol = kt * BN;
        #pragma unroll
        for (int mt = 0; mt < 2; mt++) {
            const int r0 = q0w + mt * 16 + g;
            #pragma unroll
            for (int nt = 0; nt < 8; nt++) {
                const float w0 = ex2f(accS[mt][nt][0]) * inv[mt][0];
                const float w1 = ex2f(accS[mt][nt][1]) * inv[mt][0];
                const float w2 = ex2f(accS[mt][nt][2]) * inv[mt][1];
                const float w3 = ex2f(accS[mt][nt][3]) * inv[mt][1];
                const int c = n0w + nt * 8 + tig * 2;
                *(float2*)(Wp + (size_t)r0 * S_ + kcol + c)       = make_float2(w0, w1);
                *(float2*)(Wp + (size_t)(r0 + 8) * S_ + kcol + c) = make_float2(w2, w3);
                *(float2*)(Ps + r0 * PP + c)       = make_float2(tf32r(w0), tf32r(w1));
                *(float2*)(Ps + (r0 + 8) * PP + c) = make_float2(tf32r(w2), tf32r(w3));
            }
        }
        __syncthreads();        // P visible to partner warp

        // ---- PV: O += P @ V (normalized P -> normalized O) ----
        const float* vb = sm + VS_OFF + (kt & 1) * VSTRIDE;
        #pragma unroll
        for (int ks = 0; ks < 16; ks++) {
            const int kk = ks * 8;
            uint32_t A[2][4];
            #pragma unroll
            for (int mt = 0; mt < 2; mt++) {
                const int r0 = q0w + mt * 16 + g;
                A[mt][0] = __float_as_uint(Ps[r0 * PP + kk + tig]);
                A[mt][1] = __float_as_uint(Ps[(r0 + 8) * PP + kk + tig]);
                A[mt][2] = __float_as_uint(Ps[r0 * PP + kk + tig + 4]);
                A[mt][3] = __float_as_uint(Ps[(r0 + 8) * PP + kk + tig + 4]);
            }
            #pragma unroll
            for (int nt = 0; nt < 4; nt++) {
                const int n0 = d0w + nt * 8 + g;
                uint32_t B[2];
                B[0] = __float_as_uint(vb[(kk + tig) * VP + n0]);
                B[1] = __float_as_uint(vb[(kk + tig + 4) * VP + n0]);
                mma8(accO[0][nt], A[0], B);
                mma8(accO[1][nt], A[1], B);
            }
        }
    }

    // ---- O store (already normalized) ----
    #pragma unroll
    for (int mt = 0; mt < 2; mt++) {
        const int r0 = q0w + mt * 16 + g;
        #pragma unroll
        for (int nt = 0; nt < 4; nt++) {
            const int c = d0w + nt * 8 + tig * 2;
            *(float2*)(Op + (size_t)r0 * D_ + c) =
                make_float2(accO[mt][nt][0], accO[mt][nt][1]);
            *(float2*)(Op + (size_t)(r0 + 8) * D_ + c) =
                make_float2(accO[mt][nt][2], accO[mt][nt][3]);
        }
    }
}

extern "C" void kernel_launch(void* const* d_in, const int* in_sizes, int n_in,
                              void* d_out, int out_size) {
    const float* Q = (const float*)d_in[0];
    const float* K = (const float*)d_in[1];
    const float* V = (const float*)d_in[2];
    float* W = (float*)d_out;
    float* O = (float*)d_out + (size_t)NH * S_ * S_;

    const int smem_bytes = SMEM_FLOATS * (int)sizeof(float);
    cudaFuncSetAttribute(attn2, cudaFuncAttributeMaxDynamicSharedMemorySize, smem_bytes);

    const size_t n4 = (size_t)NH * S_ * D_ / 4;     // 1048576 float4s
    prep<<<(unsigned)(n4 / NT), NT>>>(Q, K, V);

    dim3 grid(S_ / BM, NH);
    attn2<<<grid, NT, smem_bytes>>>(W, O);
}